// round 17
// baseline (speedup 1.0000x reference)
#include <cuda_runtime.h>
#include <cuda_fp16.h>
#include <math.h>
#include <stdint.h>

#define NB 2
#define NW 8
#define NN 10000
#define NF 5
#define NH 128
#define NBW 16          /* NB*NW */
#define NBN 20000       /* NB*NN */
#define NE_MAX 80000
#define NBLK 592        /* persistent grid: 4 CTAs/SM x 148 SMs */
#define NMB 157         /* LSTM m-blocks of 128 rows */
#define NTASK (NMB * 8) /* LSTM tasks per step */
#define NG2SL 158       /* GCN2 tasks per slice: 79 mb x 2 nb */
#define NG2 (16 * NG2SL)/* all GCN2 tasks */
#define NTOT (NG2 + NW * NTASK + NMB)

/* ---------------- scratch (device globals; no allocations allowed) -------- */
__device__ int   d_is64;
__device__ float d_dinv[NN];
__device__ int   d_cnt[NN];
__device__ int   d_rowptr[NN + 1];
__device__ int   d_cursor[NN];
__device__ int   d_colsrc[NE_MAX];
__device__ float d_xagg[NBW * NN * NF];
/* fp16 planes, k-pairs packed in u32 (elem 2j low half, 2j+1 high) */
__device__ uint32_t d_h1x[NBW * NN * 64];   /* gcn1 output (pre-aggregation) */
__device__ uint32_t d_h1p[NBW * NN * 64];   /* gathered layer-2 input */
__device__ uint32_t d_h2p[NBW * NN * 64];   /* gcn2 output (lstm input) */
__device__ uint32_t d_hb0[NBN * 64];        /* lstm hidden, ping */
__device__ uint32_t d_hb1[NBN * 64];        /* lstm hidden, pong */
__device__ uint32_t d_g2p[64 * NH];         /* gcn2 weight [k2][n] */
__device__ uint32_t d_btp[128 * 512];       /* lstm BT [k2][col'], col'=h*4+gate */
__device__ float d_bsum[512];               /* gate-interleaved bias */
__device__ float d_cbuf[NBN * NH];
/* dynamic scheduling state */
__device__ int d_task;
__device__ int d_done[NMB];
__device__ int d_g2done[NW];

__device__ __forceinline__ float sigf(float x) { return 1.0f / (1.0f + __expf(-x)); }

__device__ __forceinline__ uint32_t pack16(float x0, float x1) {
    uint32_t h;
    asm("cvt.rn.f16x2.f32 %0, %1, %2;" : "=r"(h) : "f"(x1), "f"(x0));
    return h;
}

__device__ __forceinline__ float2 unpack16(uint32_t u) {
    __half2 h = *reinterpret_cast<__half2*>(&u);
    return __half22float2(h);
}

__device__ __forceinline__ void cpa16(uint32_t saddr, const void* g) {
    asm volatile("cp.async.cg.shared.global [%0], [%1], 16;\n" :: "r"(saddr), "l"(g));
}

/* edge_index may be int32 or int64. Dispatch via device flag set in k_init. */
__device__ __forceinline__ int edge_at(const void* ei, int E, int which, int e) {
    if (d_is64) return (int)((const long long*)ei)[(size_t)which * E + e];
    return ((const int*)ei)[(size_t)which * E + e];
}

/* ------- init: zero cnt + int64-vs-int32 detection (block 0) ------------- */
__global__ void k_init(const int* __restrict__ ei32) {
    int idx = blockIdx.x * blockDim.x + threadIdx.x;
    if (idx < NN) d_cnt[idx] = 0;
    if (blockIdx.x == 0) {
        int t = threadIdx.x;
        int nz = 0;
        for (int i = 2 * t + 1; i < 4096; i += 2048) nz |= ei32[i];
        __shared__ int s;
        if (t == 0) s = 0;
        __syncthreads();
        if (nz) atomicOr(&s, 1);
        __syncthreads();
        if (t == 0) d_is64 = s ? 0 : 1;
    }
}

__global__ void k_count(const void* __restrict__ ei, int E) {
    int e = blockIdx.x * blockDim.x + threadIdx.x;
    if (e < E) {
        int dst = edge_at(ei, E, 1, e);
        if (dst >= 0 && dst < NN) atomicAdd(&d_cnt[dst], 1);
    }
}

/* warp-shuffle single-block scan (1024 threads, 10 items each) */
__global__ void k_scan() {
    const int IPT = 10;
    int t = threadIdx.x, lane = t & 31, w = t >> 5;
    int base = t * IPT;
    int loc[IPT];
    int s = 0;
#pragma unroll
    for (int j = 0; j < IPT; j++) {
        int idx = base + j;
        int c = (idx < NN) ? d_cnt[idx] : 0;
        loc[j] = c; s += c;
    }
    int v = s;
#pragma unroll
    for (int off = 1; off < 32; off <<= 1) {
        int u = __shfl_up_sync(0xffffffffu, v, off);
        if (lane >= off) v += u;
    }
    __shared__ int wsum[32];
    if (lane == 31) wsum[w] = v;
    __syncthreads();
    if (w == 0) {
        int x = wsum[lane];
#pragma unroll
        for (int off = 1; off < 32; off <<= 1) {
            int u = __shfl_up_sync(0xffffffffu, x, off);
            if (lane >= off) x += u;
        }
        wsum[lane] = x;
    }
    __syncthreads();
    int run = v - s + (w ? wsum[w - 1] : 0);
#pragma unroll
    for (int j = 0; j < IPT; j++) {
        int idx = base + j;
        if (idx < NN) {
            d_rowptr[idx] = run;
            d_cursor[idx] = run;
            d_dinv[idx] = rsqrtf((float)(loc[j] + 1));
            run += loc[j];
        }
    }
    if (t == 1023) d_rowptr[NN] = run;
}

__global__ void k_fill(const void* __restrict__ ei, int E) {
    int e = blockIdx.x * blockDim.x + threadIdx.x;
    if (e < E) {
        int dst = edge_at(ei, E, 1, e);
        int src = edge_at(ei, E, 0, e);
        if (dst >= 0 && dst < NN && src >= 0 && src < NN) {
            int pos = atomicAdd(&d_cursor[dst], 1);
            d_colsrc[pos] = src;
        }
    }
}

/* ---------------- GCN1 aggregation: thread per (bw,node), 5 feats -------- */
__global__ void k_aggx(const float* __restrict__ x) {
    int r = blockIdx.x * blockDim.x + threadIdx.x;
    if (r >= NBW * NN) return;
    int n = r % NN;
    int bw = r / NN;
    float di = d_dinv[n];
    const float* xs = x + (size_t)(bw * NN + n) * NF;
    float acc[NF];
    float w0 = di * di;
#pragma unroll
    for (int f = 0; f < NF; f++) acc[f] = xs[f] * w0;
    int s0 = d_rowptr[n], s1 = d_rowptr[n + 1];
    for (int e = s0; e < s1; e++) {
        int s = __ldg(&d_colsrc[e]);
        float w = __ldg(&d_dinv[s]) * di;
        const float* xv = x + (size_t)(bw * NN + s) * NF;
#pragma unroll
        for (int f = 0; f < NF; f++) acc[f] = fmaf(xv[f], w, acc[f]);
    }
    float* o = d_xagg + (size_t)r * NF;
#pragma unroll
    for (int f = 0; f < NF; f++) o[f] = acc[f];
}

/* ---------------- GCN1 transform: x@W1+b, relu -> packed fp16 (coalesced) */
__global__ void k_gcn1(const float* __restrict__ w1, const float* __restrict__ b1) {
    int idx = blockIdx.x * blockDim.x + threadIdx.x;
    if (idx >= NBW * NN * 64) return;
    int j = idx & 63;
    int r = idx >> 6;
    const float* xr = &d_xagg[r * NF];
    float2 bb = *(const float2*)&b1[2 * j];
    float a0 = bb.x, a1 = bb.y;
#pragma unroll
    for (int f = 0; f < NF; f++) {
        float xv = xr[f];
        float2 wv = *(const float2*)&w1[f * NH + 2 * j];
        a0 = fmaf(xv, wv.x, a0);
        a1 = fmaf(xv, wv.y, a1);
    }
    d_h1x[idx] = pack16(fmaxf(a0, 0.f), fmaxf(a1, 0.f));
}

/* ---------------- GCN2 aggregation (fp16 in/out, 4 rows per block) ------- */
__global__ void k_gather64() {
    int r = blockIdx.x * 4 + (threadIdx.x >> 6);
    int j = threadIdx.x & 63;
    if (r >= NBW * NN) return;
    int n = r % NN;
    int bwBase = r - n;
    float di = d_dinv[n];
    float2 acc = unpack16(d_h1x[(size_t)r * 64 + j]);
    acc.x *= di * di; acc.y *= di * di;
    int s0 = d_rowptr[n], s1 = d_rowptr[n + 1];
    for (int e = s0; e < s1; e++) {
        int s = __ldg(&d_colsrc[e]);
        float w = __ldg(&d_dinv[s]) * di;
        float2 v = unpack16(__ldg(&d_h1x[(size_t)(bwBase + s) * 64 + j]));
        acc.x = fmaf(v.x, w, acc.x);
        acc.y = fmaf(v.y, w, acc.y);
    }
    d_h1p[(size_t)r * 64 + j] = pack16(acc.x, acc.y);
}

/* ---------------- fused prep: weights, bias, state zero, sched reset ----- */
__global__ void k_prep_all(const float* __restrict__ g2w,
                           const float* __restrict__ wih, const float* __restrict__ whh,
                           const float* __restrict__ bih, const float* __restrict__ bhh) {
    int idx = blockIdx.x * blockDim.x + threadIdx.x;
    if (idx == 0) d_task = 0;
    if (idx < NMB) d_done[idx] = 0;
    if (idx < NW) d_g2done[idx] = 0;
    if (idx < 128 * 512) {
        int k2 = idx >> 9, col = idx & 511;
        int j = (col & 3) * 128 + (col >> 2);
        float a, b;
        if (k2 < 64) { a = wih[j * 128 + 2 * k2]; b = wih[j * 128 + 2 * k2 + 1]; }
        else { int kk = k2 - 64; a = whh[j * 128 + 2 * kk]; b = whh[j * 128 + 2 * kk + 1]; }
        d_btp[idx] = pack16(a, b);
    }
    if (idx < 64 * NH) {
        int k2 = idx >> 7, n = idx & 127;
        d_g2p[idx] = pack16(g2w[(2 * k2) * NH + n], g2w[(2 * k2 + 1) * NH + n]);
    }
    if (idx < 512) {
        int j = (idx & 3) * 128 + (idx >> 2);
        d_bsum[idx] = bih[j] + bhh[j];
    }
    if (idx < NBN * NH) d_cbuf[idx] = 0.0f;
    if (idx < NBN * 64) d_hb0[idx] = 0u;
}

/* ---------------- persistent mega-kernel: GCN2 + LSTM + decoder ----------
   One monotonic task stream:
     [0, NG2):           GCN2 tiles, w-major slice order; publish d_g2done[w]
     [NG2, NG2+8*NTASK): LSTM tiles (t-major); wait d_g2done[t]==316 and
                         d_done[mb]>=8t; publish d_done[mb]
     [.., +NMB):         decoder m-blocks; wait d_done[mb]==64
   Every wait targets strictly-earlier tasks => deadlock-free.           */
__global__ __launch_bounds__(256, 4)
void k_persist(const float* __restrict__ g2b,
               const float* __restrict__ dw1, const float* __restrict__ db1,
               const float* __restrict__ dw2, const float* __restrict__ db2,
               float* __restrict__ out) {
    extern __shared__ uint32_t sm[];
    __shared__ int s_task;

    int tid = threadIdx.x;
    int lane = tid & 31, wid = tid >> 5;
    int wm = wid & 3, wn = wid >> 2;
    int g = lane >> 2, tq = lane & 3;
    int arow = tid >> 1, half = tid & 1;
    int bk2 = tid >> 4, nb4 = (tid & 15) * 4;

    uint32_t smbase = (uint32_t)__cvta_generic_to_shared(sm);
    uint32_t sAoff = (arow * 20 + half * 8) * 4;
    uint32_t sBoff = (2560 + bk2 * 72 + nb4) * 4;

    for (;;) {
        if (tid == 0) s_task = atomicAdd(&d_task, 1);
        __syncthreads();
        int task = s_task;
        if (task >= NTOT) break;

        /* ================= decoder task ================= */
        if (task >= NG2 + NW * NTASK) {
            int mb = task - NG2 - NW * NTASK;
            if (tid == 0) {
                while (atomicAdd(&d_done[mb], 0) < 8 * NW) __nanosleep(32);
            }
            __syncthreads();
#pragma unroll 1
            for (int pass = 0; pass < 16; pass++) {
                int row = mb * 128 + pass * 8 + wid;
                if (row < NBN) {
                    float acc0 = db1[lane], acc1 = db1[lane + 32];
                    const uint32_t* hr = d_hb0 + (size_t)row * 64;
#pragma unroll 8
                    for (int k2 = 0; k2 < 64; k2++) {
                        float2 v = unpack16(__ldg(&hr[k2]));
                        acc0 = fmaf(v.x, __ldg(&dw1[(2 * k2) * 64 + lane]), acc0);
                        acc1 = fmaf(v.x, __ldg(&dw1[(2 * k2) * 64 + lane + 32]), acc1);
                        acc0 = fmaf(v.y, __ldg(&dw1[(2 * k2 + 1) * 64 + lane]), acc0);
                        acc1 = fmaf(v.y, __ldg(&dw1[(2 * k2 + 1) * 64 + lane + 32]), acc1);
                    }
                    float val = fmaxf(acc0, 0.f) * dw2[lane] + fmaxf(acc1, 0.f) * dw2[lane + 32];
#pragma unroll
                    for (int off = 16; off > 0; off >>= 1)
                        val += __shfl_down_sync(0xffffffffu, val, off);
                    if (lane == 0) out[row] = val + db2[0];
                }
            }
            continue;
        }

        /* ============ GEMM task setup (GCN2 or LSTM) ============ */
        bool isLstm = (task >= NG2);
        int m0, n0, NIT, Nst, mlimit, mb = 0, t = 0, j = 0, w = 0;
        const uint32_t *A0, *A1, *Bp;
        if (isLstm) {
            int r = task - NG2;
            t = r / NTASK;
            r -= t * NTASK;
            mb = r >> 3; j = r & 7;
            m0 = mb * 128; n0 = j * 64;
            NIT = 8; Nst = 512; mlimit = NBN;
            Bp = d_btp;
            if (tid == 0) {
                while (atomicAdd(&d_g2done[t], 0) < 2 * NG2SL) __nanosleep(32);
                if (t > 0) while (atomicAdd(&d_done[mb], 0) < 8 * t) __nanosleep(32);
            }
            __syncthreads();
            int amc = m0 + arow; if (amc >= NBN) amc = NBN - 1;
            int b = amc / NN, n = amc - b * NN;
            A0 = d_h2p + ((size_t)(b * NW + t) * NN + n) * 64;
            A1 = ((t & 1) ? d_hb1 : d_hb0) + (size_t)amc * 64;
        } else {
            int s = task / NG2SL;
            int r = task - s * NG2SL;
            int mb2 = r >> 1, nb = r & 1;
            w = s >> 1;
            int b = s & 1;
            int sbase = (b * NW + w) * NN;
            m0 = sbase + mb2 * 128; n0 = nb * 64;
            NIT = 4; Nst = NH; mlimit = sbase + NN;
            Bp = d_g2p;
            int amc = m0 + arow; if (amc >= mlimit) amc = mlimit - 1;
            A0 = d_h1p + (size_t)amc * 64;
            A1 = A0;
        }

        float c[2][4][4];
#pragma unroll
        for (int i = 0; i < 2; i++)
#pragma unroll
            for (int jj = 0; jj < 4; jj++)
#pragma unroll
                for (int q = 0; q < 4; q++) c[i][jj][q] = 0.0f;

        auto stage = [&](int buf, int iter) {
            uint32_t sb = smbase + (uint32_t)buf * 3712 * 4;
            int k2b = iter * 16;
            const uint32_t* a = (iter >= 4) ? (A1 + (k2b - 64) + half * 8)
                                            : (A0 + k2b + half * 8);
            cpa16(sb + sAoff, a);
            cpa16(sb + sAoff + 16, a + 4);
            cpa16(sb + sBoff, Bp + (size_t)(k2b + bk2) * Nst + n0 + nb4);
            asm volatile("cp.async.commit_group;\n");
        };

        stage(0, 0);
        for (int iter = 0; iter < NIT; iter++) {
            int buf = iter & 1;
            if (iter + 1 < NIT) {
                stage(buf ^ 1, iter + 1);
                asm volatile("cp.async.wait_group 1;\n");
            } else {
                asm volatile("cp.async.wait_group 0;\n");
            }
            __syncthreads();
            const uint32_t* sA = sm + buf * 3712;
            const uint32_t* sB = sA + 2560;
#pragma unroll
            for (int s = 0; s < 2; s++) {
                uint32_t a[2][4], bb[4][2];
                int kb = s * 8 + tq;
#pragma unroll
                for (int mt = 0; mt < 2; mt++) {
                    int rr = wm * 32 + mt * 16 + g;
                    a[mt][0] = sA[rr * 20 + kb];
                    a[mt][1] = sA[(rr + 8) * 20 + kb];
                    a[mt][2] = sA[rr * 20 + kb + 4];
                    a[mt][3] = sA[(rr + 8) * 20 + kb + 4];
                }
#pragma unroll
                for (int nt = 0; nt < 4; nt++) {
                    int col = wn * 32 + nt * 8 + g;
                    bb[nt][0] = sB[kb * 72 + col];
                    bb[nt][1] = sB[(kb + 4) * 72 + col];
                }
#pragma unroll
                for (int mt = 0; mt < 2; mt++)
#pragma unroll
                    for (int nt = 0; nt < 4; nt++) {
                        asm volatile(
                            "mma.sync.aligned.m16n8k16.row.col.f32.f16.f16.f32 "
                            "{%0,%1,%2,%3}, {%4,%5,%6,%7}, {%8,%9}, {%0,%1,%2,%3};\n"
                            : "+f"(c[mt][nt][0]), "+f"(c[mt][nt][1]),
                              "+f"(c[mt][nt][2]), "+f"(c[mt][nt][3])
                            : "r"(a[mt][0]), "r"(a[mt][1]), "r"(a[mt][2]), "r"(a[mt][3]),
                              "r"(bb[nt][0]), "r"(bb[nt][1]));
                    }
            }
            __syncthreads();
        }

        if (isLstm) {
            /* ---- fused LSTM cell epilogue: two 64-row passes ---- */
            uint32_t* Hw = (t & 1) ? d_hb0 : d_hb1;
            float* sf = (float*)sm;   /* [64 rows][68 cols] fp32 gates */
            int h0 = j * 16;
#pragma unroll
            for (int p = 0; p < 2; p++) {
                int sr = wm * 16 + g;
#pragma unroll
                for (int nt = 0; nt < 4; nt++) {
                    int lc = wn * 32 + nt * 8 + tq * 2;
                    float bb0 = d_bsum[n0 + lc], bb1 = d_bsum[n0 + lc + 1];
                    *(float2*)&sf[sr * 68 + lc] =
                        make_float2(c[p][nt][0] + bb0, c[p][nt][1] + bb1);
                    *(float2*)&sf[(sr + 8) * 68 + lc] =
                        make_float2(c[p][nt][2] + bb0, c[p][nt][3] + bb1);
                }
                __syncthreads();
#pragma unroll
                for (int it = 0; it < 2; it++) {
                    int idx = tid + it * 256;
                    int lr = idx >> 3;
                    int hp2 = idx & 7;
                    int gm = m0 + (lr >> 4) * 32 + p * 16 + (lr & 15);
                    if (gm < NBN) {
                        float4 gA = *(float4*)&sf[lr * 68 + hp2 * 8];
                        float4 gB = *(float4*)&sf[lr * 68 + hp2 * 8 + 4];
                        int hg = h0 + 2 * hp2;
                        int ci = gm * NH + hg;
                        float2 cp = __ldcg((const float2*)&d_cbuf[ci]);
                        float c0n = sigf(gA.y) * cp.x + sigf(gA.x) * tanhf(gA.z);
                        float c1n = sigf(gB.y) * cp.y + sigf(gB.x) * tanhf(gB.z);
                        float h0n = sigf(gA.w) * tanhf(c0n);
                        float h1n = sigf(gB.w) * tanhf(c1n);
                        __stcg((float2*)&d_cbuf[ci], make_float2(c0n, c1n));
                        Hw[(size_t)gm * 64 + (hg >> 1)] = pack16(h0n, h1n);
                    }
                }
                __syncthreads();
            }
            __threadfence();
            __syncthreads();
            if (tid == 0) atomicAdd(&d_done[mb], 1);
        } else {
            /* ---- GCN2 epilogue: relu + pack to h2 plane ---- */
#pragma unroll
            for (int mt = 0; mt < 2; mt++) {
                int r0 = m0 + wm * 32 + mt * 16 + g;
#pragma unroll
                for (int nt = 0; nt < 4; nt++) {
                    int col = n0 + wn * 32 + nt * 8 + tq * 2;
                    float bb0 = g2b[col], bb1 = g2b[col + 1];
                    if (r0 < mlimit) {
                        float v0 = fmaxf(c[mt][nt][0] + bb0, 0.f);
                        float v1 = fmaxf(c[mt][nt][1] + bb1, 0.f);
                        d_h2p[(size_t)r0 * 64 + (col >> 1)] = pack16(v0, v1);
                    }
                    if (r0 + 8 < mlimit) {
                        float v2 = fmaxf(c[mt][nt][2] + bb0, 0.f);
                        float v3 = fmaxf(c[mt][nt][3] + bb1, 0.f);
                        d_h2p[(size_t)(r0 + 8) * 64 + (col >> 1)] = pack16(v2, v3);
                    }
                }
            }
            __threadfence();
            __syncthreads();
            if (tid == 0) atomicAdd(&d_g2done[w], 1);
        }
    }
}

/* ---------------- host entry --------------------------------------------- */
extern "C" void kernel_launch(void* const* d_in, const int* in_sizes, int n_in,
                              void* d_out, int out_size) {
    const float* x    = (const float*)d_in[0];
    const void*  ei   = d_in[1];
    const float* g1w  = (const float*)d_in[2];
    const float* g1b  = (const float*)d_in[3];
    const float* g2w  = (const float*)d_in[4];
    const float* g2b  = (const float*)d_in[5];
    const float* wih  = (const float*)d_in[6];
    const float* whh  = (const float*)d_in[7];
    const float* bih  = (const float*)d_in[8];
    const float* bhh  = (const float*)d_in[9];
    const float* dw1  = (const float*)d_in[10];
    const float* db1  = (const float*)d_in[11];
    const float* dw2  = (const float*)d_in[12];
    const float* db2  = (const float*)d_in[13];
    float* out = (float*)d_out;
    int E = in_sizes[1] / 2;

    const int SMEM = 2 * 3712 * 4;   /* 29696 bytes */
    cudaFuncSetAttribute(k_persist, cudaFuncAttributeMaxDynamicSharedMemorySize, SMEM);

    /* graph preprocessing */
    k_init<<<(NN + 1023) / 1024, 1024>>>((const int*)ei);
    k_count<<<(E + 255) / 256, 256>>>(ei, E);
    k_scan<<<1, 1024>>>();
    k_fill<<<(E + 255) / 256, 256>>>(ei, E);

    /* GCN1 */
    k_aggx<<<(NBW * NN + 255) / 256, 256>>>(x);
    k_gcn1<<<(NBW * NN * 64 + 255) / 256, 256>>>(g1w, g1b);

    /* weight prep + state zero + scheduler reset (fused) */
    k_prep_all<<<(NBN * NH + 255) / 256, 256>>>(g2w, wih, whh, bih, bhh);

    /* GCN2 aggregation */
    k_gather64<<<NBW * NN / 4, 256>>>();

    /* GCN2 GEMM + LSTM (8 steps) + decoder: one persistent launch */
    k_persist<<<NBLK, 256, SMEM>>>(g2b, dw1, db1, dw2, db2, out);
}